// round 10
// baseline (speedup 1.0000x reference)
#include <cuda_runtime.h>
#include <cfloat>

#define NB    2
#define CC    256
#define HH    64
#define WW    64
#define KK    128
#define PH    7
#define PW    7

// NHWC scratch: [2, 64, 64, 256] floats = 8.4 MB
__device__ float g_xt[NB * HH * WW * CC];

// ---------------- Kernel 1: NCHW -> NHWC transpose ----------------
__global__ __launch_bounds__(256) void transpose_kernel(const float* __restrict__ x)
{
    __shared__ float tile[32][33];
    int b   = blockIdx.z;
    int hw0 = blockIdx.x * 32;
    int c0  = blockIdx.y * 32;

    const float* src = x    + (size_t)b * CC * (HH * WW);
    float*       dst = g_xt + (size_t)b * (HH * WW) * CC;

    #pragma unroll
    for (int i = 0; i < 4; ++i) {
        int c = c0 + threadIdx.y + i * 8;
        tile[threadIdx.y + i * 8][threadIdx.x] = src[(size_t)c * (HH * WW) + hw0 + threadIdx.x];
    }
    __syncthreads();
    #pragma unroll
    for (int i = 0; i < 4; ++i) {
        int hw = hw0 + threadIdx.y + i * 8;
        dst[(size_t)hw * CC + c0 + threadIdx.x] = tile[threadIdx.x][threadIdx.y + i * 8];
    }
}

// ---------------- Kernel 2: ROI max-pool, warp-per-bin, 4 pixels/instr ----------------
// Block = (k, cg in 0..7 [32-ch group], bin-row i). 7 warps; warp j pools bin (i,j).
// Lane = po*8 + cq: po = pixel offset 0..3, cq = channel quad 0..7 (float4).
// One LDG.128 covers 4 channels; a warp instruction covers 4 pixels x 32 channels.
__global__ __launch_bounds__(224) void roipool_pix4_kernel(
    const float* __restrict__ rois,  // [K, 5]
    float* __restrict__ out)         // [K, C, 7, 7]
{
    __shared__ float4 stage[PW][8];  // [j][cq] -> 32 channels per j

    int bid = blockIdx.x;
    int k   = bid / (8 * PH);
    int rem = bid - k * (8 * PH);
    int cg  = rem / PH;          // 32-channel group 0..7
    int i   = rem - cg * PH;     // bin row
    int j    = threadIdx.x >> 5; // warp -> bin col
    int lane = threadIdx.x & 31;
    int po   = lane >> 3;        // pixel offset 0..3
    int cq   = lane & 7;         // channel quad 0..7

    const float* r = rois + k * 5;
    int b  = (int)r[0];
    // IEEE RN multiply (0.0625 exact), round half-to-even like jnp.round
    int x1 = (int)rintf(__fmul_rn(r[1], 0.0625f));
    int y1 = (int)rintf(__fmul_rn(r[2], 0.0625f));
    int x2 = (int)rintf(__fmul_rn(r[3], 0.0625f));
    int y2 = (int)rintf(__fmul_rn(r[4], 0.0625f));

    int roi_w = max(x2 - x1 + 1, 1);
    int roi_h = max(y2 - y1 + 1, 1);

    // XLA rewrites (x / 7) -> x * RN(1/7); RN(1/7) = 0x3E124925
    const float RECIP7 = __int_as_float(0x3E124925);
    float bw = __fmul_rn((float)roi_w, RECIP7);
    float bh = __fmul_rn((float)roi_h, RECIP7);

    int hs = min(max((int)floorf(__fmul_rn((float)i,       bh)) + y1, 0), HH);
    int he = min(max((int)ceilf (__fmul_rn((float)(i + 1), bh)) + y1, 0), HH);
    int ws = min(max((int)floorf(__fmul_rn((float)j,       bw)) + x1, 0), WW);
    int we = min(max((int)ceilf (__fmul_rn((float)(j + 1), bw)) + x1, 0), WW);

    bool nonempty = (hs < he) && (ws < we);
    float4 acc = make_float4(-FLT_MAX, -FLT_MAX, -FLT_MAX, -FLT_MAX);

    if (nonempty) {
        // float4-unit base for this 32-channel slice; pixel p at p*64 + cq
        const float4* base = (const float4*)(g_xt + (size_t)b * (HH * WW) * CC + cg * 32) + cq;
        for (int h = hs; h < he; ++h) {
            const float4* rowp = base + (size_t)(h * WW) * 64;
            #pragma unroll 2
            for (int wq = ws; wq < we; wq += 4) {
                int w = wq + po;
                if (w < we) {
                    float4 v = __ldg(rowp + (size_t)w * 64);
                    acc.x = fmaxf(acc.x, v.x);
                    acc.y = fmaxf(acc.y, v.y);
                    acc.z = fmaxf(acc.z, v.z);
                    acc.w = fmaxf(acc.w, v.w);
                }
            }
        }
    }

    // Reduce across the 4 pixel groups (lanes 8 apart)
    #pragma unroll
    for (int d = 8; d <= 16; d <<= 1) {
        acc.x = fmaxf(acc.x, __shfl_xor_sync(0xFFFFFFFF, acc.x, d));
        acc.y = fmaxf(acc.y, __shfl_xor_sync(0xFFFFFFFF, acc.y, d));
        acc.z = fmaxf(acc.z, __shfl_xor_sync(0xFFFFFFFF, acc.z, d));
        acc.w = fmaxf(acc.w, __shfl_xor_sync(0xFFFFFFFF, acc.w, d));
    }
    if (!nonempty) acc = make_float4(0.f, 0.f, 0.f, 0.f);

    if (po == 0) stage[j][cq] = acc;   // lanes 0..7 hold quads 0..7
    __syncthreads();

    // Store: out[k, cg*32 + c, i, j]; 224 elements, one per thread
    float* o = out + (size_t)k * (CC * PH * PW) + (size_t)cg * 32 * (PH * PW) + i * PW;
    int idx = threadIdx.x;                 // 0..223
    int c   = idx / PW;                    // 0..31
    int jj  = idx - c * PW;                // 0..6
    const float* st = (const float*)&stage[jj][0];  // [cq][4] = 32 floats, channel-ordered
    o[(size_t)c * (PH * PW) + jj] = st[c];
}

extern "C" void kernel_launch(void* const* d_in, const int* in_sizes, int n_in,
                              void* d_out, int out_size)
{
    const float* x    = (const float*)d_in[0];
    const float* rois = (const float*)d_in[1];
    if (n_in >= 2 && in_sizes[0] < in_sizes[1]) {
        x    = (const float*)d_in[1];
        rois = (const float*)d_in[0];
    }
    float* out = (float*)d_out;

    dim3 tgrid(HH * WW / 32, CC / 32, NB);   // (128, 8, 2)
    dim3 tblk(32, 8);
    transpose_kernel<<<tgrid, tblk>>>(x);

    roipool_pix4_kernel<<<KK * 8 * PH, 224>>>(rois, out);  // 7168 blocks
}

// round 11
// speedup vs baseline: 1.2961x; 1.2961x over previous
#include <cuda_runtime.h>
#include <cfloat>

#define NB    2
#define CC    256
#define HH    64
#define WW    64
#define KK    128
#define PH    7
#define PW    7

// NHWC scratch: [2, 64, 64, 256] floats = 8.4 MB
__device__ float g_xt[NB * HH * WW * CC];

// ---------------- Kernel 1: NCHW -> NHWC transpose ----------------
__global__ __launch_bounds__(256) void transpose_kernel(const float* __restrict__ x)
{
    __shared__ float tile[32][33];
    int b   = blockIdx.z;
    int hw0 = blockIdx.x * 32;
    int c0  = blockIdx.y * 32;

    const float* src = x    + (size_t)b * CC * (HH * WW);
    float*       dst = g_xt + (size_t)b * (HH * WW) * CC;

    #pragma unroll
    for (int i = 0; i < 4; ++i) {
        int c = c0 + threadIdx.y + i * 8;
        tile[threadIdx.y + i * 8][threadIdx.x] = src[(size_t)c * (HH * WW) + hw0 + threadIdx.x];
    }
    __syncthreads();
    #pragma unroll
    for (int i = 0; i < 4; ++i) {
        int hw = hw0 + threadIdx.y + i * 8;
        dst[(size_t)hw * CC + c0 + threadIdx.x] = tile[threadIdx.x][threadIdx.y + i * 8];
    }
}

// ---------------- Kernel 2: ROI max-pool ----------------
// Block = (k, bin-row i). 14 warps: warp = (j, h-parity).
// Lane = cq (channel quad). Per pixel the warp issues 2 LDG.128 covering all
// 256 channels. Pixels batched 4 at a time with clamp-duplication -> 8
// independent loads in flight per batch, no predication.
__global__ __launch_bounds__(448) void roipool_k11(
    const float* __restrict__ rois,  // [K, 5]
    float* __restrict__ out)         // [K, C, 7, 7]
{
    // stage[j][parity][c] : 7*2*256 floats = 14 KB
    __shared__ float stage[PW][2][CC];

    int k = blockIdx.x / PH;
    int i = blockIdx.x - k * PH;

    int warp = threadIdx.x >> 5;   // 0..13
    int lane = threadIdx.x & 31;   // = cq
    int j    = warp % PW;          // bin col
    int par  = warp / PW;          // 0,1

    const float* r = rois + k * 5;
    int b  = (int)r[0];
    // IEEE RN multiply (0.0625 exact), round half-to-even like jnp.round
    int x1 = (int)rintf(__fmul_rn(r[1], 0.0625f));
    int y1 = (int)rintf(__fmul_rn(r[2], 0.0625f));
    int x2 = (int)rintf(__fmul_rn(r[3], 0.0625f));
    int y2 = (int)rintf(__fmul_rn(r[4], 0.0625f));

    int roi_w = max(x2 - x1 + 1, 1);
    int roi_h = max(y2 - y1 + 1, 1);

    // XLA rewrites (x / 7) -> x * RN(1/7); RN(1/7) = 0x3E124925
    const float RECIP7 = __int_as_float(0x3E124925);
    float bw = __fmul_rn((float)roi_w, RECIP7);
    float bh = __fmul_rn((float)roi_h, RECIP7);

    int hs = min(max((int)floorf(__fmul_rn((float)i,       bh)) + y1, 0), HH);
    int he = min(max((int)ceilf (__fmul_rn((float)(i + 1), bh)) + y1, 0), HH);
    int ws = min(max((int)floorf(__fmul_rn((float)j,       bw)) + x1, 0), WW);
    int we = min(max((int)ceilf (__fmul_rn((float)(j + 1), bw)) + x1, 0), WW);

    float4 a0 = make_float4(-FLT_MAX, -FLT_MAX, -FLT_MAX, -FLT_MAX);
    float4 a1 = a0;

    if (hs < he && ws < we) {
        // float4 units; channel-half 0 at +cq, half 1 at +32+cq
        const float4* fbase = (const float4*)(g_xt + (size_t)b * (HH * WW) * CC) + lane;
        int wlast = we - 1;
        for (int h = hs + par; h < he; h += 2) {
            const float4* rowp = fbase + (size_t)(h * WW) * 64;
            for (int w = ws; w < we; w += 4) {
                int w0 = w;
                int w1 = min(w + 1, wlast);
                int w2 = min(w + 2, wlast);
                int w3 = min(w + 3, wlast);
                float4 p0 = __ldg(rowp + (size_t)w0 * 64);
                float4 q0 = __ldg(rowp + (size_t)w0 * 64 + 32);
                float4 p1 = __ldg(rowp + (size_t)w1 * 64);
                float4 q1 = __ldg(rowp + (size_t)w1 * 64 + 32);
                float4 p2 = __ldg(rowp + (size_t)w2 * 64);
                float4 q2 = __ldg(rowp + (size_t)w2 * 64 + 32);
                float4 p3 = __ldg(rowp + (size_t)w3 * 64);
                float4 q3 = __ldg(rowp + (size_t)w3 * 64 + 32);
                a0.x = fmaxf(fmaxf(a0.x, p0.x), fmaxf(fmaxf(p1.x, p2.x), p3.x));
                a0.y = fmaxf(fmaxf(a0.y, p0.y), fmaxf(fmaxf(p1.y, p2.y), p3.y));
                a0.z = fmaxf(fmaxf(a0.z, p0.z), fmaxf(fmaxf(p1.z, p2.z), p3.z));
                a0.w = fmaxf(fmaxf(a0.w, p0.w), fmaxf(fmaxf(p1.w, p2.w), p3.w));
                a1.x = fmaxf(fmaxf(a1.x, q0.x), fmaxf(fmaxf(q1.x, q2.x), q3.x));
                a1.y = fmaxf(fmaxf(a1.y, q0.y), fmaxf(fmaxf(q1.y, q2.y), q3.y));
                a1.z = fmaxf(fmaxf(a1.z, q0.z), fmaxf(fmaxf(q1.z, q2.z), q3.z));
                a1.w = fmaxf(fmaxf(a1.w, q0.w), fmaxf(fmaxf(q1.w, q2.w), q3.w));
            }
        }
    }

    ((float4*)&stage[j][par][0])[lane]      = a0;  // channels 4*cq..4*cq+3
    ((float4*)&stage[j][par][128])[lane]    = a1;  // channels 128+...
    __syncthreads();

    // Store 256*7 outputs; recompute per-j emptiness (cheap, regs available)
    for (int t = threadIdx.x; t < CC * PW; t += 448) {
        int c  = t / PW;
        int j2 = t - c * PW;
        int ws2 = min(max((int)floorf(__fmul_rn((float)j2,       bw)) + x1, 0), WW);
        int we2 = min(max((int)ceilf (__fmul_rn((float)(j2 + 1), bw)) + x1, 0), WW);
        float v = 0.0f;
        if (hs < he && ws2 < we2)
            v = fmaxf(stage[j2][0][c], stage[j2][1][c]);
        out[(size_t)k * (CC * PH * PW) + (size_t)c * (PH * PW) + i * PW + j2] = v;
    }
}

extern "C" void kernel_launch(void* const* d_in, const int* in_sizes, int n_in,
                              void* d_out, int out_size)
{
    const float* x    = (const float*)d_in[0];
    const float* rois = (const float*)d_in[1];
    if (n_in >= 2 && in_sizes[0] < in_sizes[1]) {
        x    = (const float*)d_in[1];
        rois = (const float*)d_in[0];
    }
    float* out = (float*)d_out;

    dim3 tgrid(HH * WW / 32, CC / 32, NB);   // (128, 8, 2)
    dim3 tblk(32, 8);
    transpose_kernel<<<tgrid, tblk>>>(x);

    roipool_k11<<<KK * PH, 448>>>(rois, out);  // 896 blocks
}